// round 13
// baseline (speedup 1.0000x reference)
#include <cuda_runtime.h>
#include <cstdint>

#define KDIM 4096
#define NDIM 4096
#define MDIM 8192
#define KT 64
#define KITERS (KDIM / KT)      // 64
#define MT 128
#define NT 256
#define THREADS 512
#define ASTRIDE 96
#define BSTRIDE 96
#define A_BUF_BYTES (MT * ASTRIDE)    // 12288
#define B_BUF_BYTES (NT * BSTRIDE)    // 24576
#define SMEM_TOTAL (2 * A_BUF_BYTES + 2 * B_BUF_BYTES)  // 73728 (dynamic)

// legal scratch: __device__ globals
__device__ int8_t gXq[(size_t)MDIM * KDIM];
__device__ int8_t gWq[(size_t)KDIM * NDIM];

// ---------------- merged input compaction: int32 -> int8 ----------------
__device__ __forceinline__ uint32_t pack4i(int4 v) {
    return (uint32_t)(uint8_t)(int8_t)v.x | ((uint32_t)(uint8_t)(int8_t)v.y << 8) |
           ((uint32_t)(uint8_t)(int8_t)v.z << 16) | ((uint32_t)(uint8_t)(int8_t)v.w << 24);
}

#define XN16 ((MDIM * KDIM) / 16)   // 2097152
#define WN16 ((KDIM * NDIM) / 16)   // 1048576

__global__ void __launch_bounds__(256)
convert2_kernel(const int4* __restrict__ x, const int4* __restrict__ w,
                uint4* __restrict__ xq, uint4* __restrict__ wq)
{
    int idx = blockIdx.x * 256 + threadIdx.x;
    const int4* s;
    uint4* d;
    if (idx < XN16) {
        s = x + (size_t)idx * 4;
        d = xq + idx;
    } else {
        int j = idx - XN16;
        s = w + (size_t)j * 4;
        d = wq + j;
    }
    uint4 out;
    out.x = pack4i(s[0]); out.y = pack4i(s[1]);
    out.z = pack4i(s[2]); out.w = pack4i(s[3]);
    *d = out;
}

// ---------------- GEMM ----------------
__device__ __forceinline__ void mma_s8(int* d, const uint32_t* a, const uint32_t* b) {
    asm volatile(
        "mma.sync.aligned.m16n8k32.row.col.s32.s8.s8.s32 "
        "{%0,%1,%2,%3}, {%4,%5,%6,%7}, {%8,%9}, {%0,%1,%2,%3};"
        : "+r"(d[0]), "+r"(d[1]), "+r"(d[2]), "+r"(d[3])
        : "r"(a[0]), "r"(a[1]), "r"(a[2]), "r"(a[3]), "r"(b[0]), "r"(b[1]));
}

__device__ __forceinline__ float quantf(int acc, float asc, float bsc) {
    float f = (float)acc * asc;
    f = f * bsc;
    int v = __float2int_rn(f);    // half-even == jnp.round
    return (float)max(-128, min(127, v));
}

__global__ void __launch_bounds__(THREADS, 1)
w8a8_imma_kernel(const float* __restrict__ Af, const float* __restrict__ Bf,
                 float* __restrict__ Out)
{
    extern __shared__ __align__(16) char sm[];

    const int tid  = threadIdx.x;
    const int lane = tid & 31;
    const int wid  = tid >> 5;          // 0..15
    const int grp  = lane >> 2;
    const int qid  = lane & 3;

    const int m0 = (int)(blockIdx.x >> 4) * MT;    // 64 m-tiles
    const int n0 = (int)(blockIdx.x & 15) * NT;    // 16 n-tiles

    const float asc = Af[0];

    const int8_t* __restrict__ X = gXq;
    const int8_t* __restrict__ W = gWq;

    char* As[2] = { sm, sm + A_BUF_BYTES };
    char* Bs[2] = { sm + 2 * A_BUF_BYTES, sm + 2 * A_BUF_BYTES + B_BUF_BYTES };

    // A copy: threads 0..255 only; 32 B each (row ar, half s_a)
    const int ar  = (tid & 255) >> 1;
    const int s_a = tid & 1;
    const bool doA = tid < 256;
    const int8_t* gA = X + (size_t)(m0 + ar) * KDIM + s_a * 32;

    // B copy: ALL 512 threads; 4 k-rows x 8 cols each (64k x 256n = 16 KB)
    const int kb  = tid & 15;           // k-chunk (k-rows kb*4..kb*4+3)
    const int nbq = tid >> 4;           // 0..31 -> cols nbq*8..+7
    const int8_t* gB = W + (size_t)(kb * 4) * NDIM + n0 + nbq * 8;
    const int q_b = kb & 7;
    const int s_b = kb >> 3;

    uint4 pa0, pa1;
    uint2 pb0, pb1, pb2, pb3;

#define PREFETCH(it)                                                          \
    {                                                                         \
        if (doA) {                                                            \
            const int8_t* a_ = gA + (size_t)(it) * KT;                        \
            pa0 = *reinterpret_cast<const uint4*>(a_);                        \
            pa1 = *reinterpret_cast<const uint4*>(a_ + 16);                   \
        }                                                                     \
        const int8_t* b_ = gB + (size_t)(it) * KT * NDIM;                     \
        pb0 = *reinterpret_cast<const uint2*>(b_);                            \
        pb1 = *reinterpret_cast<const uint2*>(b_ + (size_t)NDIM);             \
        pb2 = *reinterpret_cast<const uint2*>(b_ + (size_t)2 * NDIM);         \
        pb3 = *reinterpret_cast<const uint2*>(b_ + (size_t)3 * NDIM);         \
    }

#define STORE_STAGE(buf)                                                      \
    {                                                                         \
        if (doA) {                                                            \
            char* arow = As[buf] + ar * ASTRIDE + s_a * 32;                   \
            *reinterpret_cast<uint4*>(arow) =                                 \
                make_uint4(pa0.x, pa1.x, pa0.y, pa1.y);                       \
            *reinterpret_cast<uint4*>(arow + 16) =                            \
                make_uint4(pa0.z, pa1.z, pa0.w, pa1.w);                       \
        }                                                                     \
        uint32_t c[8];                                                        \
        {                                                                     \
            uint32_t t0 = __byte_perm(pb0.x, pb1.x, 0x5140);                  \
            uint32_t t1 = __byte_perm(pb0.x, pb1.x, 0x7362);                  \
            uint32_t t2 = __byte_perm(pb2.x, pb3.x, 0x5140);                  \
            uint32_t t3 = __byte_perm(pb2.x, pb3.x, 0x7362);                  \
            c[0] = __byte_perm(t0, t2, 0x5410);                               \
            c[1] = __byte_perm(t0, t2, 0x7632);                               \
            c[2] = __byte_perm(t1, t3, 0x5410);                               \
            c[3] = __byte_perm(t1, t3, 0x7632);                               \
        }                                                                     \
        {                                                                     \
            uint32_t t0 = __byte_perm(pb0.y, pb1.y, 0x5140);                  \
            uint32_t t1 = __byte_perm(pb0.y, pb1.y, 0x7362);                  \
            uint32_t t2 = __byte_perm(pb2.y, pb3.y, 0x5140);                  \
            uint32_t t3 = __byte_perm(pb2.y, pb3.y, 0x7362);                  \
            c[4] = __byte_perm(t0, t2, 0x5410);                               \
            c[5] = __byte_perm(t0, t2, 0x7632);                               \
            c[6] = __byte_perm(t1, t3, 0x5410);                               \
            c[7] = __byte_perm(t1, t3, 0x7632);                               \
        }                                                                     \
        char* bb_ = Bs[buf] + s_b * 32 + (q_b & 3) * 8 + ((q_b & 4) ? 4 : 0); \
        _Pragma("unroll")                                                     \
        for (int ii = 0; ii < 8; ii++) {                                      \
            int idx = (ii + nbq) & 7;                                         \
            *reinterpret_cast<uint32_t*>(bb_ + (nbq * 8 + idx) * BSTRIDE) = c[idx]; \
        }                                                                     \
    }

    const int mw = (wid >> 2) * 32;     // 4 m-tiles of 32
    const int nw = (wid & 3) * 64;      // 4 n-groups of 64

    int acc[2][8][4];
#pragma unroll
    for (int mt = 0; mt < 2; mt++)
#pragma unroll
        for (int nt = 0; nt < 8; nt++)
#pragma unroll
            for (int r = 0; r < 4; r++) acc[mt][nt][r] = 0;

    PREFETCH(0);
    STORE_STAGE(0);
    __syncthreads();

#pragma unroll 1
    for (int it = 0; it < KITERS; it++) {
        const int buf = it & 1;
        if (it + 1 < KITERS) PREFETCH(it + 1);

#pragma unroll
        for (int kstep = 0; kstep < 2; kstep++) {
            uint32_t a[2][4];
#pragma unroll
            for (int mt = 0; mt < 2; mt++) {
                const char* p = As[buf] + (mw + mt * 16 + grp) * ASTRIDE +
                                kstep * 32 + qid * 8;
                uint2 lo = *reinterpret_cast<const uint2*>(p);
                uint2 hi = *reinterpret_cast<const uint2*>(p + 8 * ASTRIDE);
                a[mt][0] = lo.x; a[mt][1] = hi.x;
                a[mt][2] = lo.y; a[mt][3] = hi.y;
            }
            uint32_t b[8][2];
#pragma unroll
            for (int nt = 0; nt < 8; nt++) {
                const char* p = Bs[buf] + (nw + nt * 8 + grp) * BSTRIDE +
                                kstep * 32 + qid * 8;
                uint2 v = *reinterpret_cast<const uint2*>(p);
                b[nt][0] = v.x; b[nt][1] = v.y;
            }
#pragma unroll
            for (int mt = 0; mt < 2; mt++)
#pragma unroll
                for (int nt = 0; nt < 8; nt++)
                    mma_s8(acc[mt][nt], a[mt], b[nt]);
        }

        if (it + 1 < KITERS) STORE_STAGE(buf ^ 1);
        __syncthreads();
    }

    // ---------------- Epilogue: float32 output ----------------
#pragma unroll
    for (int mt = 0; mt < 2; mt++) {
        const int r0 = m0 + mw + mt * 16 + grp;
#pragma unroll
        for (int nt = 0; nt < 8; nt++) {
            const int col = n0 + nw + nt * 8 + qid * 2;
            const float2 bb = *reinterpret_cast<const float2*>(Bf + col);
            const int* v = acc[mt][nt];
            float2 lo = make_float2(quantf(v[0], asc, bb.x), quantf(v[1], asc, bb.y));
            float2 hi = make_float2(quantf(v[2], asc, bb.x), quantf(v[3], asc, bb.y));
            *reinterpret_cast<float2*>(Out + (size_t)r0 * NDIM + col) = lo;
            *reinterpret_cast<float2*>(Out + (size_t)(r0 + 8) * NDIM + col) = hi;
        }
    }
}

extern "C" void kernel_launch(void* const* d_in, const int* in_sizes, int n_in,
                              void* d_out, int out_size)
{
    // Measured (R10): positional x, weight, a, b; x/w int32, a/b f32, out f32.
    const int4*  X  = (const int4*)d_in[0];
    const int4*  W  = (const int4*)d_in[1];
    const float* Af = (const float*)d_in[2];
    const float* Bf = (const float*)d_in[3];
    float* Out = (float*)d_out;

    uint4* xq; cudaGetSymbolAddress((void**)&xq, gXq);
    uint4* wq; cudaGetSymbolAddress((void**)&wq, gWq);

    convert2_kernel<<<(XN16 + WN16) / 256, 256>>>(X, W, xq, wq);

    cudaFuncSetAttribute(w8a8_imma_kernel,
                         cudaFuncAttributeMaxDynamicSharedMemorySize, SMEM_TOTAL);

    const int grid = (MDIM / MT) * (NDIM / NT);  // 64 * 16 = 1024
    w8a8_imma_kernel<<<grid, THREADS, SMEM_TOTAL>>>(Af, Bf, Out);
}

// round 14
// speedup vs baseline: 1.1098x; 1.1098x over previous
#include <cuda_runtime.h>
#include <cstdint>

#define KDIM 4096
#define NDIM 4096
#define MDIM 8192
#define KT 128
#define KITERS (KDIM / KT)      // 32
#define MT 128
#define NT 128
#define THREADS 256
#define ASTRIDE 144             // 128B row + 16B pad; 36 words ≡ 4 mod 32
#define BSTRIDE 144
#define A_BUF_BYTES (MT * ASTRIDE)    // 18432
#define B_BUF_BYTES (NT * BSTRIDE)    // 18432
#define SMEM_TOTAL (2 * A_BUF_BYTES + 2 * B_BUF_BYTES)  // 73728 (dynamic)

// legal scratch: __device__ globals
__device__ int8_t gXq[(size_t)MDIM * KDIM];
__device__ int8_t gWq[(size_t)KDIM * NDIM];

// ---------------- merged input compaction: int32 -> int8 ----------------
__device__ __forceinline__ uint32_t pack4i(int4 v) {
    return (uint32_t)(uint8_t)(int8_t)v.x | ((uint32_t)(uint8_t)(int8_t)v.y << 8) |
           ((uint32_t)(uint8_t)(int8_t)v.z << 16) | ((uint32_t)(uint8_t)(int8_t)v.w << 24);
}

#define XN16 ((MDIM * KDIM) / 16)   // 2097152
#define WN16 ((KDIM * NDIM) / 16)   // 1048576

__global__ void __launch_bounds__(256)
convert2_kernel(const int4* __restrict__ x, const int4* __restrict__ w,
                uint4* __restrict__ xq, uint4* __restrict__ wq)
{
    int idx = blockIdx.x * 256 + threadIdx.x;
    const int4* s;
    uint4* d;
    if (idx < XN16) {
        s = x + (size_t)idx * 4;
        d = xq + idx;
    } else {
        int j = idx - XN16;
        s = w + (size_t)j * 4;
        d = wq + j;
    }
    uint4 out;
    out.x = pack4i(s[0]); out.y = pack4i(s[1]);
    out.z = pack4i(s[2]); out.w = pack4i(s[3]);
    *d = out;
}

// ---------------- GEMM ----------------
__device__ __forceinline__ void mma_s8(int* d, const uint32_t* a, const uint32_t* b) {
    asm volatile(
        "mma.sync.aligned.m16n8k32.row.col.s32.s8.s8.s32 "
        "{%0,%1,%2,%3}, {%4,%5,%6,%7}, {%8,%9}, {%0,%1,%2,%3};"
        : "+r"(d[0]), "+r"(d[1]), "+r"(d[2]), "+r"(d[3])
        : "r"(a[0]), "r"(a[1]), "r"(a[2]), "r"(a[3]), "r"(b[0]), "r"(b[1]));
}

__device__ __forceinline__ float quantf(int acc, float asc, float bsc) {
    float f = (float)acc * asc;
    f = f * bsc;
    int v = __float2int_rn(f);    // half-even == jnp.round
    return (float)max(-128, min(127, v));
}

// SMEM layout: per row, 4 k-groups of 32B (ksteps 0..3). Within a group,
// chunk q (4B, q=0..7) lives at (q&3)*8 + (q>>2)*4, so the MMA fragment
// pair (q, q+4) is one aligned 8B word -> single LDS.64 per fragment.

__global__ void __launch_bounds__(THREADS, 1)
w8a8_imma_kernel(const float* __restrict__ Af, const float* __restrict__ Bf,
                 float* __restrict__ Out)
{
    extern __shared__ __align__(16) char sm[];

    const int tid  = threadIdx.x;
    const int lane = tid & 31;
    const int wid  = tid >> 5;
    const int grp  = lane >> 2;
    const int qid  = lane & 3;

    const int m0 = (int)(blockIdx.x >> 5) * MT;
    const int n0 = (int)(blockIdx.x & 31) * NT;

    const float asc = Af[0];

    const int8_t* __restrict__ X = gXq;
    const int8_t* __restrict__ W = gWq;

    char* As[2] = { sm, sm + A_BUF_BYTES };
    char* Bs[2] = { sm + 2 * A_BUF_BYTES, sm + 2 * A_BUF_BYTES + B_BUF_BYTES };

    // A copy: each thread 64B of one row (ksteps 2*s_a .. 2*s_a+1)
    const int ar  = tid >> 1;
    const int s_a = tid & 1;
    const int8_t* gA = X + (size_t)(m0 + ar) * KDIM + s_a * 64;

    // B copy: each thread 8 k-rows x 8 cols (chunks kb*2, kb*2+1)
    const int kb = tid >> 4;            // 0..15 -> k-rows kb*8..+7
    const int nb = tid & 15;            // cols nb*8..+7
    const int8_t* gB = W + (size_t)(kb * 8) * NDIM + n0 + nb * 8;

    uint4 pa[4];
    uint2 pb[8];

#define PREFETCH(it)                                                          \
    {                                                                         \
        const int8_t* a_ = gA + (size_t)(it) * KT;                            \
        _Pragma("unroll")                                                     \
        for (int j = 0; j < 4; j++)                                           \
            pa[j] = *reinterpret_cast<const uint4*>(a_ + j * 16);             \
        const int8_t* b_ = gB + (size_t)(it) * KT * NDIM;                     \
        _Pragma("unroll")                                                     \
        for (int r = 0; r < 8; r++)                                           \
            pb[r] = *reinterpret_cast<const uint2*>(b_ + (size_t)r * NDIM);   \
    }

#define BTRANS(h, out)                                                        \
    {                                                                         \
        uint32_t t0 = __byte_perm(pb[4*(h)+0].x, pb[4*(h)+1].x, 0x5140);      \
        uint32_t t1 = __byte_perm(pb[4*(h)+0].x, pb[4*(h)+1].x, 0x7362);      \
        uint32_t t2 = __byte_perm(pb[4*(h)+2].x, pb[4*(h)+3].x, 0x5140);      \
        uint32_t t3 = __byte_perm(pb[4*(h)+2].x, pb[4*(h)+3].x, 0x7362);      \
        out[0] = __byte_perm(t0, t2, 0x5410);                                 \
        out[1] = __byte_perm(t0, t2, 0x7632);                                 \
        out[2] = __byte_perm(t1, t3, 0x5410);                                 \
        out[3] = __byte_perm(t1, t3, 0x7632);                                 \
        t0 = __byte_perm(pb[4*(h)+0].y, pb[4*(h)+1].y, 0x5140);               \
        t1 = __byte_perm(pb[4*(h)+0].y, pb[4*(h)+1].y, 0x7362);               \
        t2 = __byte_perm(pb[4*(h)+2].y, pb[4*(h)+3].y, 0x5140);               \
        t3 = __byte_perm(pb[4*(h)+2].y, pb[4*(h)+3].y, 0x7362);               \
        out[4] = __byte_perm(t0, t2, 0x5410);                                 \
        out[5] = __byte_perm(t0, t2, 0x7632);                                 \
        out[6] = __byte_perm(t1, t3, 0x5410);                                 \
        out[7] = __byte_perm(t1, t3, 0x7632);                                 \
    }

#define STORE_STAGE(buf)                                                      \
    {                                                                         \
        char* arow = As[buf] + ar * ASTRIDE + s_a * 64;                       \
        *reinterpret_cast<uint4*>(arow) =                                     \
            make_uint4(pa[0].x, pa[1].x, pa[0].y, pa[1].y);                   \
        *reinterpret_cast<uint4*>(arow + 16) =                                \
            make_uint4(pa[0].z, pa[1].z, pa[0].w, pa[1].w);                   \
        *reinterpret_cast<uint4*>(arow + 32) =                                \
            make_uint4(pa[2].x, pa[3].x, pa[2].y, pa[3].y);                   \
        *reinterpret_cast<uint4*>(arow + 48) =                                \
            make_uint4(pa[2].z, pa[3].z, pa[2].w, pa[3].w);                   \
        _Pragma("unroll")                                                     \
        for (int h = 0; h < 2; h++) {                                         \
            uint32_t c[8];                                                    \
            BTRANS(h, c);                                                     \
            const int cidx = kb * 2 + h;                                      \
            const int qq = cidx & 7;                                          \
            char* bb_ = Bs[buf] + (cidx >> 3) * 32 + (qq & 3) * 8 +           \
                        ((qq >> 2) ? 4 : 0);                                  \
            _Pragma("unroll")                                                 \
            for (int ii = 0; ii < 8; ii++) {                                  \
                int idx = (ii + nb) & 7;                                      \
                *reinterpret_cast<uint32_t*>(bb_ + (nb * 8 + idx) * BSTRIDE) = c[idx]; \
            }                                                                 \
        }                                                                     \
    }

    const int mw = (wid >> 1) * 32;
    const int nw = (wid & 1) * 64;

    int acc[2][8][4];
#pragma unroll
    for (int mt = 0; mt < 2; mt++)
#pragma unroll
        for (int nt = 0; nt < 8; nt++)
#pragma unroll
            for (int r = 0; r < 4; r++) acc[mt][nt][r] = 0;

    PREFETCH(0);
    STORE_STAGE(0);
    __syncthreads();

#pragma unroll 1
    for (int it = 0; it < KITERS; it++) {
        const int buf = it & 1;
        if (it + 1 < KITERS) PREFETCH(it + 1);

#pragma unroll
        for (int kstep = 0; kstep < 4; kstep++) {
            uint32_t a[2][4];
#pragma unroll
            for (int mt = 0; mt < 2; mt++) {
                const char* p = As[buf] + (mw + mt * 16 + grp) * ASTRIDE +
                                kstep * 32 + qid * 8;
                uint2 lo = *reinterpret_cast<const uint2*>(p);
                uint2 hi = *reinterpret_cast<const uint2*>(p + 8 * ASTRIDE);
                a[mt][0] = lo.x; a[mt][1] = hi.x;
                a[mt][2] = lo.y; a[mt][3] = hi.y;
            }
            uint32_t b[8][2];
#pragma unroll
            for (int nt = 0; nt < 8; nt++) {
                const char* p = Bs[buf] + (nw + nt * 8 + grp) * BSTRIDE +
                                kstep * 32 + qid * 8;
                uint2 v = *reinterpret_cast<const uint2*>(p);
                b[nt][0] = v.x; b[nt][1] = v.y;
            }
#pragma unroll
            for (int mt = 0; mt < 2; mt++)
#pragma unroll
                for (int nt = 0; nt < 8; nt++)
                    mma_s8(acc[mt][nt], a[mt], b[nt]);
        }

        if (it + 1 < KITERS) STORE_STAGE(buf ^ 1);
        __syncthreads();
    }

    // ---------------- Epilogue: float32 output ----------------
#pragma unroll
    for (int mt = 0; mt < 2; mt++) {
        const int r0 = m0 + mw + mt * 16 + grp;
#pragma unroll
        for (int nt = 0; nt < 8; nt++) {
            const int col = n0 + nw + nt * 8 + qid * 2;
            const float2 bb = *reinterpret_cast<const float2*>(Bf + col);
            const int* v = acc[mt][nt];
            float2 lo = make_float2(quantf(v[0], asc, bb.x), quantf(v[1], asc, bb.y));
            float2 hi = make_float2(quantf(v[2], asc, bb.x), quantf(v[3], asc, bb.y));
            *reinterpret_cast<float2*>(Out + (size_t)r0 * NDIM + col) = lo;
            *reinterpret_cast<float2*>(Out + (size_t)(r0 + 8) * NDIM + col) = hi;
        }
    }
}

extern "C" void kernel_launch(void* const* d_in, const int* in_sizes, int n_in,
                              void* d_out, int out_size)
{
    // Measured (R10): positional x, weight, a, b; x/w int32, a/b f32, out f32.
    const int4*  X  = (const int4*)d_in[0];
    const int4*  W  = (const int4*)d_in[1];
    const float* Af = (const float*)d_in[2];
    const float* Bf = (const float*)d_in[3];
    float* Out = (float*)d_out;

    uint4* xq; cudaGetSymbolAddress((void**)&xq, gXq);
    uint4* wq; cudaGetSymbolAddress((void**)&wq, gWq);

    convert2_kernel<<<(XN16 + WN16) / 256, 256>>>(X, W, xq, wq);

    cudaFuncSetAttribute(w8a8_imma_kernel,
                         cudaFuncAttributeMaxDynamicSharedMemorySize, SMEM_TOTAL);

    const int grid = (MDIM / MT) * (NDIM / NT);  // 64 * 32 = 2048
    w8a8_imma_kernel<<<grid, THREADS, SMEM_TOTAL>>>(Af, Bf, Out);
}

// round 15
// speedup vs baseline: 1.2592x; 1.1346x over previous
#include <cuda_runtime.h>
#include <cstdint>

#define KDIM 4096
#define NDIM 4096
#define MDIM 8192
#define KT 64
#define KITERS (KDIM / KT)      // 64
#define MT 128
#define NT 128
#define THREADS 256
#define STRIDE 80               // 64B row + 16B pad; 20 words -> conflict-free
#define A_TILE (MT * STRIDE)    // 10240
#define STAGE_BYTES (2 * A_TILE)  // A + B = 20480
#define STAGES 3
#define SMEM_TOTAL (STAGES * STAGE_BYTES)  // 61440

// legal scratch
__device__ int8_t gXq[(size_t)MDIM * KDIM];
__device__ int8_t gWt[(size_t)NDIM * KDIM];   // W transposed: [N][K], K-major

__device__ __forceinline__ uint32_t pack4i(int4 v) {
    return (uint32_t)(uint8_t)(int8_t)v.x | ((uint32_t)(uint8_t)(int8_t)v.y << 8) |
           ((uint32_t)(uint8_t)(int8_t)v.z << 16) | ((uint32_t)(uint8_t)(int8_t)v.w << 24);
}

#define XN16 ((MDIM * KDIM) / 16)   // 2097152

// X: linear int32 -> int8 pack
__global__ void __launch_bounds__(256)
convertX_kernel(const int4* __restrict__ x, uint4* __restrict__ xq)
{
    int idx = blockIdx.x * 256 + threadIdx.x;
    const int4* s = x + (size_t)idx * 4;
    uint4 out;
    out.x = pack4i(s[0]); out.y = pack4i(s[1]);
    out.z = pack4i(s[2]); out.w = pack4i(s[3]);
    xq[idx] = out;
}

// W: int32 [K][N] -> int8 [N][K] (pack + transpose, 4x4 byte micro-tiles)
__global__ void __launch_bounds__(256)
transposeW_kernel(const int* __restrict__ w, int8_t* __restrict__ wt)
{
    const int tid = threadIdx.x;
    const int bk = blockIdx.x & 31;          // 32 k-tiles of 128
    const int bn = blockIdx.x >> 5;          // 32 n-tiles of 128
    const int k0 = bk * 128, n0 = bn * 128;
    const int kg = tid & 7;                  // k-group within 32-row band
    const int ng = tid >> 3;                 // 0..31 n-group

#pragma unroll
    for (int band = 0; band < 4; band++) {
        const int k = k0 + band * 32 + kg * 4;
        const int n = n0 + ng * 4;
        uint32_t p[4];
#pragma unroll
        for (int j = 0; j < 4; j++)
            p[j] = pack4i(*reinterpret_cast<const int4*>(w + (size_t)(k + j) * NDIM + n));
        uint32_t t0 = __byte_perm(p[0], p[1], 0x5140);
        uint32_t t1 = __byte_perm(p[0], p[1], 0x7362);
        uint32_t t2 = __byte_perm(p[2], p[3], 0x5140);
        uint32_t t3 = __byte_perm(p[2], p[3], 0x7362);
        uint32_t o0 = __byte_perm(t0, t2, 0x5410);
        uint32_t o1 = __byte_perm(t0, t2, 0x7632);
        uint32_t o2 = __byte_perm(t1, t3, 0x5410);
        uint32_t o3 = __byte_perm(t1, t3, 0x7632);
        *reinterpret_cast<uint32_t*>(wt + (size_t)(n + 0) * KDIM + k) = o0;
        *reinterpret_cast<uint32_t*>(wt + (size_t)(n + 1) * KDIM + k) = o1;
        *reinterpret_cast<uint32_t*>(wt + (size_t)(n + 2) * KDIM + k) = o2;
        *reinterpret_cast<uint32_t*>(wt + (size_t)(n + 3) * KDIM + k) = o3;
    }
}

// ---------------- GEMM ----------------
__device__ __forceinline__ void mma_s8(int* d, const uint32_t* a, const uint32_t* b) {
    asm volatile(
        "mma.sync.aligned.m16n8k32.row.col.s32.s8.s8.s32 "
        "{%0,%1,%2,%3}, {%4,%5,%6,%7}, {%8,%9}, {%0,%1,%2,%3};"
        : "+r"(d[0]), "+r"(d[1]), "+r"(d[2]), "+r"(d[3])
        : "r"(a[0]), "r"(a[1]), "r"(a[2]), "r"(a[3]), "r"(b[0]), "r"(b[1]));
}

__device__ __forceinline__ float quantf(int acc, float asc, float bsc) {
    float f = (float)acc * asc;
    f = f * bsc;
    int v = __float2int_rn(f);    // half-even == jnp.round
    return (float)max(-128, min(127, v));
}

__device__ __forceinline__ void cp16(uint32_t dst, const void* src) {
    asm volatile("cp.async.cg.shared.global [%0], [%1], 16;"
                 :: "r"(dst), "l"(src));
}

__global__ void __launch_bounds__(THREADS, 2)
w8a8_imma_kernel(const float* __restrict__ Af, const float* __restrict__ Bf,
                 float* __restrict__ Out)
{
    extern __shared__ __align__(16) char sm[];
    const uint32_t smem_base = (uint32_t)__cvta_generic_to_shared(sm);

    const int tid  = threadIdx.x;
    const int lane = tid & 31;
    const int wid  = tid >> 5;
    const int grp  = lane >> 2;
    const int qid  = lane & 3;

    const int m0 = (int)(blockIdx.x >> 5) * MT;
    const int n0 = (int)(blockIdx.x & 31) * NT;

    const float asc = Af[0];

    // copy mapping: row = tid>>1, 32B half = tid&1 (two 16B chunks each)
    const int crow = tid >> 1;
    const int chc  = (tid & 1) * 32;
    const int8_t* srcA = gXq + (size_t)(m0 + crow) * KDIM + chc;
    const int8_t* srcB = gWt + (size_t)(n0 + crow) * KDIM + chc;
    const uint32_t dstA = smem_base + crow * STRIDE + chc;
    const uint32_t dstB = dstA + A_TILE;

#define ISSUE(stage, it)                                                      \
    {                                                                         \
        const uint32_t so = (stage) * STAGE_BYTES;                            \
        const int8_t* a_ = srcA + (size_t)(it) * KT;                          \
        const int8_t* b_ = srcB + (size_t)(it) * KT;                          \
        cp16(dstA + so,      a_);                                             \
        cp16(dstA + so + 16, a_ + 16);                                        \
        cp16(dstB + so,      b_);                                             \
        cp16(dstB + so + 16, b_ + 16);                                        \
        asm volatile("cp.async.commit_group;" ::: "memory");                  \
    }

    const int mw = (wid >> 1) * 32;
    const int nw = (wid & 1) * 64;

    int acc[2][8][4];
#pragma unroll
    for (int mt = 0; mt < 2; mt++)
#pragma unroll
        for (int nt = 0; nt < 8; nt++)
#pragma unroll
            for (int r = 0; r < 4; r++) acc[mt][nt][r] = 0;

    // prologue: stages 0..STAGES-2
    ISSUE(0, 0);
    ISSUE(1, 1);

#pragma unroll 1
    for (int it = 0; it < KITERS; it++) {
        const int cur = it % STAGES;

        asm volatile("cp.async.wait_group 1;" ::: "memory");
        __syncthreads();
        if (it + STAGES - 1 < KITERS) ISSUE((it + STAGES - 1) % STAGES, it + STAGES - 1);

        const char* Ab = sm + cur * STAGE_BYTES;
        const char* Bb = Ab + A_TILE;

#pragma unroll
        for (int kstep = 0; kstep < 2; kstep++) {
            uint32_t a[2][4];
#pragma unroll
            for (int mt = 0; mt < 2; mt++) {
                const char* p = Ab + (mw + mt * 16 + grp) * STRIDE +
                                kstep * 32 + qid * 4;
                a[mt][0] = *reinterpret_cast<const uint32_t*>(p);
                a[mt][1] = *reinterpret_cast<const uint32_t*>(p + 8 * STRIDE);
                a[mt][2] = *reinterpret_cast<const uint32_t*>(p + 16);
                a[mt][3] = *reinterpret_cast<const uint32_t*>(p + 8 * STRIDE + 16);
            }
            uint32_t b[8][2];
#pragma unroll
            for (int nt = 0; nt < 8; nt++) {
                const char* p = Bb + (nw + nt * 8 + grp) * STRIDE +
                                kstep * 32 + qid * 4;
                b[nt][0] = *reinterpret_cast<const uint32_t*>(p);
                b[nt][1] = *reinterpret_cast<const uint32_t*>(p + 16);
            }
#pragma unroll
            for (int mt = 0; mt < 2; mt++)
#pragma unroll
                for (int nt = 0; nt < 8; nt++)
                    mma_s8(acc[mt][nt], a[mt], b[nt]);
        }
        __syncthreads();
    }

    // ---------------- Epilogue: float32 output ----------------
#pragma unroll
    for (int mt = 0; mt < 2; mt++) {
        const int r0 = m0 + mw + mt * 16 + grp;
#pragma unroll
        for (int nt = 0; nt < 8; nt++) {
            const int col = n0 + nw + nt * 8 + qid * 2;
            const float2 bb = *reinterpret_cast<const float2*>(Bf + col);
            const int* v = acc[mt][nt];
            float2 lo = make_float2(quantf(v[0], asc, bb.x), quantf(v[1], asc, bb.y));
            float2 hi = make_float2(quantf(v[2], asc, bb.x), quantf(v[3], asc, bb.y));
            *reinterpret_cast<float2*>(Out + (size_t)r0 * NDIM + col) = lo;
            *reinterpret_cast<float2*>(Out + (size_t)(r0 + 8) * NDIM + col) = hi;
        }
    }
}

extern "C" void kernel_launch(void* const* d_in, const int* in_sizes, int n_in,
                              void* d_out, int out_size)
{
    // Measured (R10): positional x, weight, a, b; x/w int32, a/b f32, out f32.
    const int4*  X  = (const int4*)d_in[0];
    const int*   W  = (const int*)d_in[1];
    const float* Af = (const float*)d_in[2];
    const float* Bf = (const float*)d_in[3];
    float* Out = (float*)d_out;

    uint4*  xq; cudaGetSymbolAddress((void**)&xq, gXq);
    int8_t* wt; cudaGetSymbolAddress((void**)&wt, gWt);

    convertX_kernel<<<XN16 / 256, 256>>>(X, xq);
    transposeW_kernel<<<1024, 256>>>(W, wt);

    cudaFuncSetAttribute(w8a8_imma_kernel,
                         cudaFuncAttributeMaxDynamicSharedMemorySize, SMEM_TOTAL);

    const int grid = (MDIM / MT) * (NDIM / NT);  // 64 * 32 = 2048
    w8a8_imma_kernel<<<grid, THREADS, SMEM_TOTAL>>>(Af, Bf, Out);
}

// round 16
// speedup vs baseline: 1.2594x; 1.0002x over previous
#include <cuda_runtime.h>
#include <cstdint>

#define KDIM 4096
#define NDIM 4096
#define MDIM 8192
#define KT 64
#define KITERS (KDIM / KT)      // 64
#define MT 128
#define NT 128
#define THREADS 256
#define STRIDE 80               // 64B row + 16B pad; conflict-free
#define A_TILE (MT * STRIDE)    // 10240
#define STAGE_BYTES (2 * A_TILE)  // 20480
#define STAGES 4
#define SMEM_TOTAL (STAGES * STAGE_BYTES)  // 81920

// legal scratch
__device__ int8_t gXq[(size_t)MDIM * KDIM];
__device__ int8_t gWt[(size_t)NDIM * KDIM];   // W transposed: [N][K], K-major

__device__ __forceinline__ uint32_t pack4i(int4 v) {
    return (uint32_t)(uint8_t)(int8_t)v.x | ((uint32_t)(uint8_t)(int8_t)v.y << 8) |
           ((uint32_t)(uint8_t)(int8_t)v.z << 16) | ((uint32_t)(uint8_t)(int8_t)v.w << 24);
}

#define XN16 ((MDIM * KDIM) / 16)   // 2097152
#define XBLOCKS (XN16 / 256)        // 8192
#define TBLOCKS 1024

// Merged pre-pass: blocks [0, XBLOCKS) pack X; blocks [XBLOCKS, +TBLOCKS) transpose W.
__global__ void __launch_bounds__(256)
prep_kernel(const int4* __restrict__ x, const int* __restrict__ w,
            uint4* __restrict__ xq, int8_t* __restrict__ wt)
{
    const int tid = threadIdx.x;
    if (blockIdx.x < XBLOCKS) {
        int idx = blockIdx.x * 256 + tid;
        const int4* s = x + (size_t)idx * 4;
        uint4 out;
        out.x = pack4i(s[0]); out.y = pack4i(s[1]);
        out.z = pack4i(s[2]); out.w = pack4i(s[3]);
        xq[idx] = out;
    } else {
        const int blk = blockIdx.x - XBLOCKS;
        const int bk = blk & 31;
        const int bn = blk >> 5;
        const int k0 = bk * 128, n0 = bn * 128;
        const int kg = tid & 7;
        const int ng = tid >> 3;
#pragma unroll
        for (int band = 0; band < 4; band++) {
            const int k = k0 + band * 32 + kg * 4;
            const int n = n0 + ng * 4;
            uint32_t p[4];
#pragma unroll
            for (int j = 0; j < 4; j++)
                p[j] = pack4i(*reinterpret_cast<const int4*>(w + (size_t)(k + j) * NDIM + n));
            uint32_t t0 = __byte_perm(p[0], p[1], 0x5140);
            uint32_t t1 = __byte_perm(p[0], p[1], 0x7362);
            uint32_t t2 = __byte_perm(p[2], p[3], 0x5140);
            uint32_t t3 = __byte_perm(p[2], p[3], 0x7362);
            *reinterpret_cast<uint32_t*>(wt + (size_t)(n + 0) * KDIM + k) = __byte_perm(t0, t2, 0x5410);
            *reinterpret_cast<uint32_t*>(wt + (size_t)(n + 1) * KDIM + k) = __byte_perm(t0, t2, 0x7632);
            *reinterpret_cast<uint32_t*>(wt + (size_t)(n + 2) * KDIM + k) = __byte_perm(t1, t3, 0x5410);
            *reinterpret_cast<uint32_t*>(wt + (size_t)(n + 3) * KDIM + k) = __byte_perm(t1, t3, 0x7632);
        }
    }
}

// ---------------- GEMM ----------------
__device__ __forceinline__ void mma_s8(int* d, const uint32_t* a, const uint32_t* b) {
    asm volatile(
        "mma.sync.aligned.m16n8k32.row.col.s32.s8.s8.s32 "
        "{%0,%1,%2,%3}, {%4,%5,%6,%7}, {%8,%9}, {%0,%1,%2,%3};"
        : "+r"(d[0]), "+r"(d[1]), "+r"(d[2]), "+r"(d[3])
        : "r"(a[0]), "r"(a[1]), "r"(a[2]), "r"(a[3]), "r"(b[0]), "r"(b[1]));
}

__device__ __forceinline__ float quantf(int acc, float asc, float bsc) {
    float f = (float)acc * asc;
    f = f * bsc;
    int v = __float2int_rn(f);    // half-even == jnp.round
    return (float)max(-128, min(127, v));
}

__device__ __forceinline__ void cp16(uint32_t dst, const void* src) {
    asm volatile("cp.async.cg.shared.global [%0], [%1], 16;"
                 :: "r"(dst), "l"(src));
}

__global__ void __launch_bounds__(THREADS, 2)
w8a8_imma_kernel(const float* __restrict__ Af, const float* __restrict__ Bf,
                 float* __restrict__ Out)
{
    extern __shared__ __align__(16) char sm[];
    const uint32_t smem_base = (uint32_t)__cvta_generic_to_shared(sm);

    const int tid  = threadIdx.x;
    const int lane = tid & 31;
    const int wid  = tid >> 5;
    const int grp  = lane >> 2;
    const int qid  = lane & 3;

    const int m0 = (int)(blockIdx.x >> 5) * MT;
    const int n0 = (int)(blockIdx.x & 31) * NT;

    const float asc = Af[0];

    const int crow = tid >> 1;
    const int chc  = (tid & 1) * 32;
    const int8_t* srcA = gXq + (size_t)(m0 + crow) * KDIM + chc;
    const int8_t* srcB = gWt + (size_t)(n0 + crow) * KDIM + chc;
    const uint32_t dstA = smem_base + crow * STRIDE + chc;
    const uint32_t dstB = dstA + A_TILE;

#define ISSUE(stage, it)                                                      \
    {                                                                         \
        const uint32_t so = (stage) * STAGE_BYTES;                            \
        const int8_t* a_ = srcA + (size_t)(it) * KT;                          \
        const int8_t* b_ = srcB + (size_t)(it) * KT;                          \
        cp16(dstA + so,      a_);                                             \
        cp16(dstA + so + 16, a_ + 16);                                        \
        cp16(dstB + so,      b_);                                             \
        cp16(dstB + so + 16, b_ + 16);                                        \
        asm volatile("cp.async.commit_group;" ::: "memory");                  \
    }

    const int mw = (wid >> 1) * 32;
    const int nw = (wid & 1) * 64;

    int acc[2][8][4];
#pragma unroll
    for (int mt = 0; mt < 2; mt++)
#pragma unroll
        for (int nt = 0; nt < 8; nt++)
#pragma unroll
            for (int r = 0; r < 4; r++) acc[mt][nt][r] = 0;

    // prologue: fill stages 0..STAGES-2
    ISSUE(0, 0);
    ISSUE(1, 1);
    ISSUE(2, 2);

#pragma unroll 1
    for (int it = 0; it < KITERS; it++) {
        const int cur = it % STAGES;

        asm volatile("cp.async.wait_group %0;" :: "n"(STAGES - 2) : "memory");
        __syncthreads();
        // Safe: the barrier above guarantees every warp finished compute(it-1),
        // and the stage written here ((it+3)%4) was last read at iter it-1.
        if (it + STAGES - 1 < KITERS)
            ISSUE((it + STAGES - 1) % STAGES, it + STAGES - 1);

        const char* Ab = sm + cur * STAGE_BYTES;
        const char* Bb = Ab + A_TILE;

#pragma unroll
        for (int kstep = 0; kstep < 2; kstep++) {
            uint32_t a[2][4];
#pragma unroll
            for (int mt = 0; mt < 2; mt++) {
                const char* p = Ab + (mw + mt * 16 + grp) * STRIDE +
                                kstep * 32 + qid * 4;
                a[mt][0] = *reinterpret_cast<const uint32_t*>(p);
                a[mt][1] = *reinterpret_cast<const uint32_t*>(p + 8 * STRIDE);
                a[mt][2] = *reinterpret_cast<const uint32_t*>(p + 16);
                a[mt][3] = *reinterpret_cast<const uint32_t*>(p + 8 * STRIDE + 16);
            }
            uint32_t b[8][2];
#pragma unroll
            for (int nt = 0; nt < 8; nt++) {
                const char* p = Bb + (nw + nt * 8 + grp) * STRIDE +
                                kstep * 32 + qid * 4;
                b[nt][0] = *reinterpret_cast<const uint32_t*>(p);
                b[nt][1] = *reinterpret_cast<const uint32_t*>(p + 16);
            }
#pragma unroll
            for (int mt = 0; mt < 2; mt++)
#pragma unroll
                for (int nt = 0; nt < 8; nt++)
                    mma_s8(acc[mt][nt], a[mt], b[nt]);
        }
        // no trailing barrier: next iter's top barrier provides the ordering
    }

    // ---------------- Epilogue: float32 output ----------------
#pragma unroll
    for (int mt = 0; mt < 2; mt++) {
        const int r0 = m0 + mw + mt * 16 + grp;
#pragma unroll
        for (int nt = 0; nt < 8; nt++) {
            const int col = n0 + nw + nt * 8 + qid * 2;
            const float2 bb = *reinterpret_cast<const float2*>(Bf + col);
            const int* v = acc[mt][nt];
            float2 lo = make_float2(quantf(v[0], asc, bb.x), quantf(v[1], asc, bb.y));
            float2 hi = make_float2(quantf(v[2], asc, bb.x), quantf(v[3], asc, bb.y));
            *reinterpret_cast<float2*>(Out + (size_t)r0 * NDIM + col) = lo;
            *reinterpret_cast<float2*>(Out + (size_t)(r0 + 8) * NDIM + col) = hi;
        }
    }
}

extern "C" void kernel_launch(void* const* d_in, const int* in_sizes, int n_in,
                              void* d_out, int out_size)
{
    // Measured (R10): positional x, weight, a, b; x/w int32, a/b f32, out f32.
    const int4*  X  = (const int4*)d_in[0];
    const int*   W  = (const int*)d_in[1];
    const float* Af = (const float*)d_in[2];
    const float* Bf = (const float*)d_in[3];
    float* Out = (float*)d_out;

    uint4*  xq; cudaGetSymbolAddress((void**)&xq, gXq);
    int8_t* wt; cudaGetSymbolAddress((void**)&wt, gWt);

    prep_kernel<<<XBLOCKS + TBLOCKS, 256>>>(X, W, xq, wt);

    cudaFuncSetAttribute(w8a8_imma_kernel,
                         cudaFuncAttributeMaxDynamicSharedMemorySize, SMEM_TOTAL);

    const int grid = (MDIM / MT) * (NDIM / NT);  // 64 * 32 = 2048
    w8a8_imma_kernel<<<grid, THREADS, SMEM_TOTAL>>>(Af, Bf, Out);
}